// round 7
// baseline (speedup 1.0000x reference)
#include <cuda_runtime.h>
#include <cstdint>

// ---------------------------------------------------------------------------
// TripletLoss, single fused persistent kernel.
//   B=384, D=256, C=48. JAX-exact gumbel via threefry2x32 (partitionable,
//   bits = x0^x1, key=[0,42]) evaluated only at semi-hard sites.
//   Phase A: per-block pair compaction (1 global atomic/block) +
//            double-buffered, float4-vectorized 32x32 distance tiles.
//   Grid barrier (144 blocks, single wave on 148 SMs).
//   Phase B: one warp per (anchor,positive) pair -> argmax, block accumulate.
//   Finalize: last-done block writes scalar and resets state for replay.
// ---------------------------------------------------------------------------

#define B 384
#define D 256
#define MARGIN 0.2f
#define TINYF 1.17549435e-38f
#define NBLK 144
#define NTHR 512
#define TILE 32
#define PITCH 36                      // floats; 144B rows -> 16B aligned float4
#define NPAIR_MAX ((B * (B - 1)) / 2)

// ---- persistent device state (restored to initial values every run) -------
__device__ float    g_dist[B * B];
__device__ int      g_pairlist[NPAIR_MAX];
__device__ int      g_npairs = 0;
__device__ float    g_total  = 0.0f;
__device__ int      g_count  = 0;
__device__ unsigned g_done   = 0;
__device__ unsigned g_barcnt = 0;
__device__ volatile unsigned g_sense = 0;

// ---- threefry2x32, JAX schedule, key = [0, 42] -----------------------------
__device__ __forceinline__ uint32_t rotl32(uint32_t x, int d) {
    return __funnelshift_l(x, x, d);
}

// noinline: executes only on semi-hard lanes; keeps phase-B loop I-cache small
__device__ __noinline__ float gumbel_at(uint32_t n) {
    // counter = (0, n) since n < 384^3 < 2^32 ; key = [0, 42]
    const uint32_t k0 = 0u, k1 = 42u;
    const uint32_t k2 = k0 ^ k1 ^ 0x1BD11BDAu;
    uint32_t x0 = 0u + k0, x1 = n + k1;
#define TF_RND(r) { x0 += x1; x1 = rotl32(x1, (r)); x1 ^= x0; }
    TF_RND(13) TF_RND(15) TF_RND(26) TF_RND(6)
    x0 += k1; x1 += k2 + 1u;
    TF_RND(17) TF_RND(29) TF_RND(16) TF_RND(24)
    x0 += k2; x1 += k0 + 2u;
    TF_RND(13) TF_RND(15) TF_RND(26) TF_RND(6)
    x0 += k0; x1 += k1 + 3u;
    TF_RND(17) TF_RND(29) TF_RND(16) TF_RND(24)
    x0 += k1; x1 += k2 + 4u;
    TF_RND(13) TF_RND(15) TF_RND(26) TF_RND(6)
    x0 += k2; x1 += k0 + 5u;
#undef TF_RND
    uint32_t bits = x0 ^ x1;   // partitionable 32-bit draw
    float f = __uint_as_float((bits >> 9) | 0x3f800000u) - 1.0f;
    float u = fmaxf(TINYF, f + TINYF);
    return -logf(-logf(u));
}

// ---- sense-reversing grid barrier (144 blocks <= 148 SMs, 1/SM resident) ---
__device__ __forceinline__ void grid_barrier() {
    __syncthreads();
    __threadfence();
    if (threadIdx.x == 0) {
        unsigned s = g_sense;
        if (atomicAdd(&g_barcnt, 1u) == gridDim.x - 1) {
            atomicExch(&g_barcnt, 0u);
            __threadfence();
            g_sense = s ^ 1u;
        } else {
            while (g_sense == s) { }
        }
    }
    __syncthreads();
}

// ---- the fused kernel --------------------------------------------------------
__global__ void __launch_bounds__(NTHR)
k_fused(const float* __restrict__ f, const int* __restrict__ labels,
        const int* __restrict__ epoch, float* __restrict__ out) {
    __shared__ float As[2][TILE][PITCH];
    __shared__ float Bs[2][TILE][PITCH];
    __shared__ int   s_lab[B];
    __shared__ int   s_pbuf[128];
    __shared__ int   s_pcnt;
    __shared__ float s_total;
    __shared__ int   s_count;

    const int tid = threadIdx.x;
    const int bid = blockIdx.x;

    if (tid < B) s_lab[tid] = labels[tid];
    if (tid == 0) { s_total = 0.0f; s_count = 0; s_pcnt = 0; }
    __syncthreads();

    // ---- phase A1: pair compaction, smem-local then one global atomic ------
#pragma unroll
    for (int e = 0; e < 2; e++) {
        int idx = bid * 1024 + e * NTHR + tid;
        int i = idx / B, p = idx - i * B;
        if (p > i && s_lab[i] == s_lab[p]) {
            int slot = atomicAdd(&s_pcnt, 1);
            s_pbuf[slot] = (i << 16) | p;
        }
    }
    __syncthreads();
    {
        __shared__ int s_base;
        if (tid == 0 && s_pcnt > 0) s_base = atomicAdd(&g_npairs, s_pcnt);
        __syncthreads();
        if (tid < s_pcnt) g_pairlist[s_base + tid] = s_pbuf[tid];
    }

    // ---- phase A2: dist tile 32x32, double-buffered, float4 smem reads -----
    {
        const int by = bid / 12, bx = bid % 12;
        const int i0 = by * TILE, j0 = bx * TILE;
        const int lr = tid >> 5;          // rows lr and lr+16
        const int lc = tid & 31;
        float acc0 = 0.0f, acc1 = 0.0f;
        float rA0, rA1, rB0, rB1;

        // preload chunk 0
        rA0 = f[(i0 + lr)      * D + lc];
        rA1 = f[(i0 + lr + 16) * D + lc];
        rB0 = f[(j0 + lr)      * D + lc];
        rB1 = f[(j0 + lr + 16) * D + lc];

#pragma unroll
        for (int c = 0; c < D / TILE; c++) {
            const int buf = c & 1;
            As[buf][lr][lc]      = rA0;
            As[buf][lr + 16][lc] = rA1;
            Bs[buf][lr][lc]      = rB0;
            Bs[buf][lr + 16][lc] = rB1;
            __syncthreads();
            if (c < D / TILE - 1) {
                const int kk = (c + 1) * TILE;
                rA0 = f[(i0 + lr)      * D + kk + lc];
                rA1 = f[(i0 + lr + 16) * D + kk + lc];
                rB0 = f[(j0 + lr)      * D + kk + lc];
                rB1 = f[(j0 + lr + 16) * D + kk + lc];
            }
#pragma unroll
            for (int k4 = 0; k4 < TILE / 4; k4++) {
                float4 b  = *(const float4*)&Bs[buf][lc][k4 * 4];      // LDS.128
                float4 a0 = *(const float4*)&As[buf][lr][k4 * 4];      // bcast
                float4 a1 = *(const float4*)&As[buf][lr + 16][k4 * 4]; // bcast
                float d;
                d = a0.x - b.x; acc0 += d * d;
                d = a0.y - b.y; acc0 += d * d;
                d = a0.z - b.z; acc0 += d * d;
                d = a0.w - b.w; acc0 += d * d;
                d = a1.x - b.x; acc1 += d * d;
                d = a1.y - b.y; acc1 += d * d;
                d = a1.z - b.z; acc1 += d * d;
                d = a1.w - b.w; acc1 += d * d;
            }
            __syncthreads();   // protect buffer reuse at c+2
        }
        g_dist[(i0 + lr)      * B + j0 + lc] = sqrtf(fmaxf(acc0, 1e-11f));
        g_dist[(i0 + lr + 16) * B + j0 + lc] = sqrtf(fmaxf(acc1, 1e-11f));
    }

    grid_barrier();

    // ---- phase B: one warp per pair ----
    const bool semi_mode = (epoch[0] > 3);
    const int lane  = tid & 31;
    const int gw    = bid * (NTHR / 32) + (tid >> 5);
    const int nwarp = gridDim.x * (NTHR / 32);
    const int np    = *(volatile int*)&g_npairs;

    float wsum = 0.0f;
    int   wcnt = 0;

    for (int q = gw; q < np; q += nwarp) {
        const int code = g_pairlist[q];
        const int i = code >> 16, p = code & 0xffff;
        const int li = s_lab[i];
        const float* drow = g_dist + i * B;
        const float dpos = drow[p];
        const uint32_t nbase = ((uint32_t)i * B + p) * B;

        float best = -3.0e38f;
        int   bidx = 0x7fffffff;
        bool  anyf = false;
#pragma unroll
        for (int s = 0; s < B / 32; s++) {
            const int k = s * 32 + lane;
            const float dik = drow[k];                 // coalesced 128B
            const bool neg = (s_lab[k] != li);
            const bool semi = semi_mode
                ? (neg && dik > dpos && dik < dpos + MARGIN) : neg;
            if (semi) {
                anyf = true;
                float base = semi_mode ? -logf(dik) : 0.0f;
                float sc = base + gumbel_at(nbase + k);
                if (sc > best || (sc == best && k < bidx)) { best = sc; bidx = k; }
            }
        }
        // warp argmax, first-index tie break (matches jnp.argmax)
#pragma unroll
        for (int off = 16; off; off >>= 1) {
            float ov = __shfl_down_sync(0xffffffffu, best, off);
            int   oi = __shfl_down_sync(0xffffffffu, bidx, off);
            if (ov > best || (ov == best && oi < bidx)) { best = ov; bidx = oi; }
        }
        const bool any = __any_sync(0xffffffffu, anyf);
        if (lane == 0 && any) {
            wsum += fmaxf(dpos - drow[bidx] + MARGIN, 0.0f);
            wcnt += 1;
        }
    }

    if (lane == 0 && wcnt > 0) {
        atomicAdd(&s_total, wsum);
        atomicAdd(&s_count, wcnt);
    }
    __syncthreads();
    if (tid == 0 && s_count > 0) {
        atomicAdd(&g_total, s_total);
        atomicAdd(&g_count, s_count);
    }

    // ---- finalize: last block writes the result & resets persistent state ---
    __threadfence();
    if (tid == 0) {
        if (atomicAdd(&g_done, 1u) == gridDim.x - 1) {
            float tot = atomicAdd(&g_total, 0.0f);   // atomic read-after-fence
            int   cnt = atomicAdd(&g_count, 0);
            out[0] = (cnt > 0) ? (tot / (float)cnt) : 0.0f;
            g_total  = 0.0f;
            g_count  = 0;
            g_npairs = 0;
            __threadfence();
            atomicExch(&g_done, 0u);
        }
    }
}

// ---- launch ------------------------------------------------------------------
extern "C" void kernel_launch(void* const* d_in, const int* in_sizes, int n_in,
                              void* d_out, int out_size) {
    const float* feat   = (const float*)d_in[0];
    const int*   labels = (const int*)d_in[1];
    const int*   epoch  = (const int*)d_in[2];
    float* out = (float*)d_out;

    k_fused<<<NBLK, NTHR>>>(feat, labels, epoch, out);
}

// round 8
// speedup vs baseline: 1.4100x; 1.4100x over previous
#include <cuda_runtime.h>
#include <cstdint>

// ---------------------------------------------------------------------------
// TripletLoss, single fused persistent kernel.
//   B=384, D=256, C=48. JAX-exact gumbel via threefry2x32 (partitionable,
//   bits = x0^x1, key=[0,42]) evaluated only at semi-hard sites.
//   Phase A: per-block pair compaction (1 global atomic/block) +
//            double-buffered, float4-vectorized 32x32 distance tiles.
//   Grid barrier (144 blocks, single wave on 148 SMs).
//   Phase B: one warp per (anchor,positive) pair -> argmax, block accumulate.
//   Finalize: last-done block writes scalar and resets state for replay.
// ---------------------------------------------------------------------------

#define B 384
#define D 256
#define MARGIN 0.2f
#define TINYF 1.17549435e-38f
#define NBLK 144
#define NTHR 512
#define TILE 32
#define PITCH 36                      // floats; 144B rows -> 16B aligned float4
#define NPAIR_MAX ((B * (B - 1)) / 2)

// ---- persistent device state (restored to initial values every run) -------
__device__ float    g_dist[B * B];
__device__ int      g_pairlist[NPAIR_MAX];
__device__ int      g_npairs = 0;
__device__ float    g_total  = 0.0f;
__device__ int      g_count  = 0;
__device__ unsigned g_done   = 0;
__device__ unsigned g_barcnt = 0;
__device__ volatile unsigned g_sense = 0;

// ---- threefry2x32, JAX schedule, key = [0, 42] -----------------------------
__device__ __forceinline__ uint32_t rotl32(uint32_t x, int d) {
    return __funnelshift_l(x, x, d);
}

// noinline: executes only on semi-hard lanes; keeps phase-B loop I-cache small
__device__ __noinline__ float gumbel_at(uint32_t n) {
    // counter = (0, n) since n < 384^3 < 2^32 ; key = [0, 42]
    const uint32_t k0 = 0u, k1 = 42u;
    const uint32_t k2 = k0 ^ k1 ^ 0x1BD11BDAu;
    uint32_t x0 = 0u + k0, x1 = n + k1;
#define TF_RND(r) { x0 += x1; x1 = rotl32(x1, (r)); x1 ^= x0; }
    TF_RND(13) TF_RND(15) TF_RND(26) TF_RND(6)
    x0 += k1; x1 += k2 + 1u;
    TF_RND(17) TF_RND(29) TF_RND(16) TF_RND(24)
    x0 += k2; x1 += k0 + 2u;
    TF_RND(13) TF_RND(15) TF_RND(26) TF_RND(6)
    x0 += k0; x1 += k1 + 3u;
    TF_RND(17) TF_RND(29) TF_RND(16) TF_RND(24)
    x0 += k1; x1 += k2 + 4u;
    TF_RND(13) TF_RND(15) TF_RND(26) TF_RND(6)
    x0 += k2; x1 += k0 + 5u;
#undef TF_RND
    uint32_t bits = x0 ^ x1;   // partitionable 32-bit draw
    float f = __uint_as_float((bits >> 9) | 0x3f800000u) - 1.0f;
    float u = fmaxf(TINYF, f + TINYF);
    return -logf(-logf(u));
}

// ---- sense-reversing grid barrier (144 blocks <= 148 SMs, 1/SM resident) ---
__device__ __forceinline__ void grid_barrier() {
    __syncthreads();
    __threadfence();
    if (threadIdx.x == 0) {
        unsigned s = g_sense;
        if (atomicAdd(&g_barcnt, 1u) == gridDim.x - 1) {
            atomicExch(&g_barcnt, 0u);
            __threadfence();
            g_sense = s ^ 1u;
        } else {
            while (g_sense == s) { }
        }
    }
    __syncthreads();
}

// ---- the fused kernel --------------------------------------------------------
__global__ void __launch_bounds__(NTHR)
k_fused(const float* __restrict__ f, const int* __restrict__ labels,
        const int* __restrict__ epoch, float* __restrict__ out) {
    __shared__ float As[2][TILE][PITCH];
    __shared__ float Bs[2][TILE][PITCH];
    __shared__ int   s_lab[B];
    __shared__ int   s_pbuf[128];
    __shared__ int   s_pcnt;
    __shared__ float s_total;
    __shared__ int   s_count;

    const int tid = threadIdx.x;
    const int bid = blockIdx.x;

    if (tid < B) s_lab[tid] = labels[tid];
    if (tid == 0) { s_total = 0.0f; s_count = 0; s_pcnt = 0; }
    __syncthreads();

    // ---- phase A1: pair compaction, smem-local then one global atomic ------
#pragma unroll
    for (int e = 0; e < 2; e++) {
        int idx = bid * 1024 + e * NTHR + tid;
        int i = idx / B, p = idx - i * B;
        if (p > i && s_lab[i] == s_lab[p]) {
            int slot = atomicAdd(&s_pcnt, 1);
            s_pbuf[slot] = (i << 16) | p;
        }
    }
    __syncthreads();
    {
        __shared__ int s_base;
        if (tid == 0 && s_pcnt > 0) s_base = atomicAdd(&g_npairs, s_pcnt);
        __syncthreads();
        if (tid < s_pcnt) g_pairlist[s_base + tid] = s_pbuf[tid];
    }

    // ---- phase A2: dist tile 32x32, double-buffered, float4 smem reads -----
    {
        const int by = bid / 12, bx = bid % 12;
        const int i0 = by * TILE, j0 = bx * TILE;
        const int lr = tid >> 5;          // rows lr and lr+16
        const int lc = tid & 31;
        float acc0 = 0.0f, acc1 = 0.0f;
        float rA0, rA1, rB0, rB1;

        // preload chunk 0
        rA0 = f[(i0 + lr)      * D + lc];
        rA1 = f[(i0 + lr + 16) * D + lc];
        rB0 = f[(j0 + lr)      * D + lc];
        rB1 = f[(j0 + lr + 16) * D + lc];

#pragma unroll
        for (int c = 0; c < D / TILE; c++) {
            const int buf = c & 1;
            As[buf][lr][lc]      = rA0;
            As[buf][lr + 16][lc] = rA1;
            Bs[buf][lr][lc]      = rB0;
            Bs[buf][lr + 16][lc] = rB1;
            __syncthreads();
            if (c < D / TILE - 1) {
                const int kk = (c + 1) * TILE;
                rA0 = f[(i0 + lr)      * D + kk + lc];
                rA1 = f[(i0 + lr + 16) * D + kk + lc];
                rB0 = f[(j0 + lr)      * D + kk + lc];
                rB1 = f[(j0 + lr + 16) * D + kk + lc];
            }
#pragma unroll
            for (int k4 = 0; k4 < TILE / 4; k4++) {
                float4 b  = *(const float4*)&Bs[buf][lc][k4 * 4];      // LDS.128
                float4 a0 = *(const float4*)&As[buf][lr][k4 * 4];      // bcast
                float4 a1 = *(const float4*)&As[buf][lr + 16][k4 * 4]; // bcast
                float d;
                d = a0.x - b.x; acc0 += d * d;
                d = a0.y - b.y; acc0 += d * d;
                d = a0.z - b.z; acc0 += d * d;
                d = a0.w - b.w; acc0 += d * d;
                d = a1.x - b.x; acc1 += d * d;
                d = a1.y - b.y; acc1 += d * d;
                d = a1.z - b.z; acc1 += d * d;
                d = a1.w - b.w; acc1 += d * d;
            }
            __syncthreads();   // protect buffer reuse at c+2
        }
        g_dist[(i0 + lr)      * B + j0 + lc] = sqrtf(fmaxf(acc0, 1e-11f));
        g_dist[(i0 + lr + 16) * B + j0 + lc] = sqrtf(fmaxf(acc1, 1e-11f));
    }

    grid_barrier();

    // ---- phase B: one warp per pair ----
    const bool semi_mode = (epoch[0] > 3);
    const int lane  = tid & 31;
    const int gw    = bid * (NTHR / 32) + (tid >> 5);
    const int nwarp = gridDim.x * (NTHR / 32);
    const int np    = *(volatile int*)&g_npairs;

    float wsum = 0.0f;
    int   wcnt = 0;

    for (int q = gw; q < np; q += nwarp) {
        const int code = g_pairlist[q];
        const int i = code >> 16, p = code & 0xffff;
        const int li = s_lab[i];
        const float* drow = g_dist + i * B;
        const float dpos = drow[p];
        const uint32_t nbase = ((uint32_t)i * B + p) * B;

        float best = -3.0e38f;
        int   bidx = 0x7fffffff;
        bool  anyf = false;
#pragma unroll
        for (int s = 0; s < B / 32; s++) {
            const int k = s * 32 + lane;
            const float dik = drow[k];                 // coalesced 128B
            const bool neg = (s_lab[k] != li);
            const bool semi = semi_mode
                ? (neg && dik > dpos && dik < dpos + MARGIN) : neg;
            if (semi) {
                anyf = true;
                float base = semi_mode ? -logf(dik) : 0.0f;
                float sc = base + gumbel_at(nbase + k);
                if (sc > best || (sc == best && k < bidx)) { best = sc; bidx = k; }
            }
        }
        // warp argmax, first-index tie break (matches jnp.argmax)
#pragma unroll
        for (int off = 16; off; off >>= 1) {
            float ov = __shfl_down_sync(0xffffffffu, best, off);
            int   oi = __shfl_down_sync(0xffffffffu, bidx, off);
            if (ov > best || (ov == best && oi < bidx)) { best = ov; bidx = oi; }
        }
        const bool any = __any_sync(0xffffffffu, anyf);
        if (lane == 0 && any) {
            wsum += fmaxf(dpos - drow[bidx] + MARGIN, 0.0f);
            wcnt += 1;
        }
    }

    if (lane == 0 && wcnt > 0) {
        atomicAdd(&s_total, wsum);
        atomicAdd(&s_count, wcnt);
    }
    __syncthreads();
    if (tid == 0 && s_count > 0) {
        atomicAdd(&g_total, s_total);
        atomicAdd(&g_count, s_count);
    }

    // ---- finalize: last block writes the result & resets persistent state ---
    __threadfence();
    if (tid == 0) {
        if (atomicAdd(&g_done, 1u) == gridDim.x - 1) {
            float tot = atomicAdd(&g_total, 0.0f);   // atomic read-after-fence
            int   cnt = atomicAdd(&g_count, 0);
            out[0] = (cnt > 0) ? (tot / (float)cnt) : 0.0f;
            g_total  = 0.0f;
            g_count  = 0;
            g_npairs = 0;
            __threadfence();
            atomicExch(&g_done, 0u);
        }
    }
}

// ---- launch ------------------------------------------------------------------
extern "C" void kernel_launch(void* const* d_in, const int* in_sizes, int n_in,
                              void* d_out, int out_size) {
    const float* feat   = (const float*)d_in[0];
    const int*   labels = (const int*)d_in[1];
    const int*   epoch  = (const int*)d_in[2];
    float* out = (float*)d_out;

    k_fused<<<NBLK, NTHR>>>(feat, labels, epoch, out);
}